// round 7
// baseline (speedup 1.0000x reference)
#include <cuda_runtime.h>
#include <math.h>
#include <stdint.h>

#define NB   2048
#define NC   9605
#define NL   20
#define NCP  9616          // NC rounded up to 16
#define BDIM 256
#define CAP  2048
#define T1   2.5f          // ~60 candidates expected for N(0,1)
#define T2   1.0f          // ~1500 candidates expected

// Scratch (no allocations allowed)
__device__ __align__(16) unsigned char d_tabs[4][NCP]; // shifted class->group
__device__ int   d_hist[4];
__device__ float d_loss[NB];
__device__ int   d_done;

__global__ void __launch_bounds__(256)
init_kernel() {
    int t0 = blockIdx.x * blockDim.x + threadIdx.x;
    if (t0 == 0) {
        d_done = 0;
        d_hist[0] = d_hist[1] = d_hist[2] = d_hist[3] = 0;
    }
    uint4* p = (uint4*)d_tabs;
    const uint4 ff = make_uint4(0xFFFFFFFFu, 0xFFFFFFFFu, 0xFFFFFFFFu, 0xFFFFFFFFu);
    for (int i = t0; i < (4 * NCP) / 16; i += gridDim.x * blockDim.x)
        p[i] = ff;
}

// Flag nonzero bytes by (offset mod 4) over the first NL*NC BYTES (safe lower
// bound under every candidate dtype width) to infer the mask dtype.
__global__ void __launch_bounds__(256)
detect_kernel(const unsigned char* __restrict__ raw) {
    const int total = NL * NC;
    const uint4* r4 = (const uint4*)raw;
    int f0 = 0, f1 = 0, f2 = 0, f3 = 0;
    int nv = total >> 4;
    for (int i = blockIdx.x * blockDim.x + threadIdx.x; i < nv;
         i += gridDim.x * blockDim.x) {
        uint4 w = __ldg(r4 + i);
        unsigned a = w.x | w.y | w.z | w.w;
        f0 |= (a & 0x000000FFu) != 0;
        f1 |= (a & 0x0000FF00u) != 0;
        f2 |= (a & 0x00FF0000u) != 0;
        f3 |= (a & 0xFF000000u) != 0;
    }
    if (blockIdx.x == 0) {
        for (int i = (nv << 4) + threadIdx.x; i < total; i += blockDim.x)
            if (raw[i]) { int m = i & 3;
                f0 |= (m == 0); f1 |= (m == 1); f2 |= (m == 2); f3 |= (m == 3); }
    }
    if (f0) atomicOr(&d_hist[0], 1);
    if (f1) atomicOr(&d_hist[1], 1);
    if (f2) atomicOr(&d_hist[2], 1);
    if (f3) atomicOr(&d_hist[3], 1);
}

__device__ __forceinline__ void tab_set(int c, unsigned char g) {
#pragma unroll
    for (int h = 0; h < 4; ++h)
        if (c >= h) d_tabs[h][c - h] = g;
}

// Fill shifted class->group tables from group_mask [L, C], honoring dtype.
__global__ void __launch_bounds__(256)
build_kernel(const void* __restrict__ maskv) {
    int h0 = d_hist[0], h1 = d_hist[1], h2 = d_hist[2], h3 = d_hist[3];
    int mode;  // 0 = uint8, 1 = int32, 2 = float32
    if (h0 && !h1 && !h2 && !h3)        mode = 1;
    else if (!h0 && !h1 && (h2 || h3))  mode = 2;
    else                                 mode = 0;

    const int total = NL * NC;
    const int gs = gridDim.x * blockDim.x;
    const int t0 = blockIdx.x * blockDim.x + threadIdx.x;

    if (mode != 0) {
        const int4* m4 = (const int4*)maskv;  // int32/float32: !=0 bit test
        int nv = total >> 2;
        for (int i = t0; i < nv; i += gs) {
            int4 w = __ldg(m4 + i);
            int base = i << 2;
#pragma unroll
            for (int u = 0; u < 4; ++u) {
                int bits = (u == 0) ? w.x : (u == 1) ? w.y : (u == 2) ? w.z : w.w;
                if (bits != 0) {
                    int idx = base + u;
                    tab_set(idx % NC, (unsigned char)(idx / NC));
                }
            }
        }
        for (int idx = (nv << 2) + t0; idx < total; idx += gs)
            if (((const int*)maskv)[idx] != 0)
                tab_set(idx % NC, (unsigned char)(idx / NC));
    } else {
        const unsigned char* m8 = (const unsigned char*)maskv;
        for (int idx = t0; idx < total; idx += gs)
            if (m8[idx])
                tab_set(idx % NC, (unsigned char)(idx / NC));
    }
}

__device__ __forceinline__ float sigmoidf_(float v) {
    return 1.0f / (1.0f + expf(-v));
}
__device__ __forceinline__ float rankl(float x1, float x2) {
    float d = x2 - x1 + 0.05f;
    float s = 1.0f / (1.0f + expf(-10.0f * d));
    return (d > 0.0f) ? 2.0f * s : s;
}
__device__ __forceinline__ unsigned fenc(float v) {
    unsigned u = __float_as_uint(v);
    return (u & 0x80000000u) ? ~u : (u | 0x80000000u);
}
__device__ __forceinline__ float fdec(unsigned u) {
    return (u & 0x80000000u) ? __uint_as_float(u ^ 0x80000000u)
                             : __uint_as_float(~u);
}

// ---------------------------------------------------------------------------
// Fused per-row pass: dense 3-stream scan of x / y / y_neg. Collects top-11
// candidates, per-group max(x) via shifted table word, and group activity via
// rare nonzero-y decode. Then threshold + loss + last-block reduction.
// ---------------------------------------------------------------------------
__global__ void __launch_bounds__(BDIM, 6)
loss_kernel(const float* __restrict__ x,
            const int*   __restrict__ y,
            const int*   __restrict__ yn,
            float*       __restrict__ out) {
    const int b   = blockIdx.x;
    const int tid = threadIdx.x;
    const float* xr  = x  + (size_t)b * NC;
    const int*   yr  = y  + (size_t)b * NC;
    const int*   ynr = yn + (size_t)b * NC;

    __shared__ unsigned s_tabw[NCP / 4];   // table shifted by `head`, word view
    __shared__ float    s_cand[CAP];
    __shared__ int      s_cnt;
    __shared__ float    s_v11;
    __shared__ unsigned s_gmax[NL];
    __shared__ int      s_act[NL];
    __shared__ int      s_an[NL];
    __shared__ int      s_last;

    if (tid == 0) s_cnt = 0;
    if (tid < NL) { s_gmax[tid] = 0u; s_act[tid] = 0; s_an[tid] = 0; }

    // vector-body geometry (x, y, yn share the same misalignment per row)
    const int head = (int)((16u - ((unsigned)(uintptr_t)xr & 15u)) & 15u) >> 2;
    const float4* xv   = (const float4*)(xr  + head);
    const int4*   yv4  = (const int4*)(yr  + head);
    const int4*   ynv4 = (const int4*)(ynr + head);
    const int nvec  = (NC - head) >> 2;
    const int tail0 = head + (nvec << 2);

    // stage pre-shifted table with uint4 loads
    {
        const uint4* src = (const uint4*)d_tabs[head];
        uint4* dst = (uint4*)s_tabw;
        for (int i = tid; i < NCP / 16; i += BDIM) dst[i] = __ldg(src + i);
    }
    __syncthreads();

    auto process = [&](const float4& v, const int4& yq, const int4& nq,
                       unsigned tw) {
        float m01 = fmaxf(v.x, v.y), m23 = fmaxf(v.z, v.w);
        if (fmaxf(m01, m23) > T1) {
            if (v.x > T1) { int p = atomicAdd(&s_cnt, 1); if (p < CAP) s_cand[p] = v.x; }
            if (v.y > T1) { int p = atomicAdd(&s_cnt, 1); if (p < CAP) s_cand[p] = v.y; }
            if (v.z > T1) { int p = atomicAdd(&s_cnt, 1); if (p < CAP) s_cand[p] = v.z; }
            if (v.w > T1) { int p = atomicAdd(&s_cnt, 1); if (p < CAP) s_cand[p] = v.w; }
        }
        if (tw != 0xFFFFFFFFu) {
            unsigned t0 =  tw        & 0xFF;
            unsigned t1 = (tw >> 8)  & 0xFF;
            unsigned t2 = (tw >> 16) & 0xFF;
            unsigned t3 = (tw >> 24) & 0xFF;
            if (t0 != 0xFF) atomicMax(&s_gmax[t0], fenc(v.x));
            if (t1 != 0xFF) atomicMax(&s_gmax[t1], fenc(v.y));
            if (t2 != 0xFF) atomicMax(&s_gmax[t2], fenc(v.z));
            if (t3 != 0xFF) atomicMax(&s_gmax[t3], fenc(v.w));
        }
        if (yq.x | yq.y | yq.z | yq.w) {
            if (yq.x) { unsigned t = tw & 0xFF;         if (t != 0xFF) atomicOr(&s_act[t], 1); }
            if (yq.y) { unsigned t = (tw >> 8) & 0xFF;  if (t != 0xFF) atomicOr(&s_act[t], 1); }
            if (yq.z) { unsigned t = (tw >> 16) & 0xFF; if (t != 0xFF) atomicOr(&s_act[t], 1); }
            if (yq.w) { unsigned t = (tw >> 24) & 0xFF; if (t != 0xFF) atomicOr(&s_act[t], 1); }
        }
        if (nq.x | nq.y | nq.z | nq.w) {
            if (nq.x) { unsigned t = tw & 0xFF;         if (t != 0xFF) atomicOr(&s_an[t], 1); }
            if (nq.y) { unsigned t = (tw >> 8) & 0xFF;  if (t != 0xFF) atomicOr(&s_an[t], 1); }
            if (nq.z) { unsigned t = (tw >> 16) & 0xFF; if (t != 0xFF) atomicOr(&s_an[t], 1); }
            if (nq.w) { unsigned t = (tw >> 24) & 0xFF; if (t != 0xFF) atomicOr(&s_an[t], 1); }
        }
    };
    auto scalar_at = [&](int c, unsigned char t) {
        float v = __ldg(xr + c);
        if (v > T1) { int p = atomicAdd(&s_cnt, 1); if (p < CAP) s_cand[p] = v; }
        if (t != 0xFF) {
            atomicMax(&s_gmax[t], fenc(v));
            if (__ldg(yr  + c)) atomicOr(&s_act[t], 1);
            if (__ldg(ynr + c)) atomicOr(&s_an[t],  1);
        }
    };

    // head scalars (classes 0..head-1, table = unshifted d_tabs[0])
    if (tid < head) scalar_at(tid, d_tabs[0][tid]);

    // main unrolled dense 3-stream body
    int i = tid;
    for (; i + BDIM < nvec; i += 2 * BDIM) {
        float4 a0 = __ldcs(xv + i);
        float4 a1 = __ldcs(xv + i + BDIM);
        int4   y0 = __ldcs(yv4 + i);
        int4   y1 = __ldcs(yv4 + i + BDIM);
        int4   n0 = __ldcs(ynv4 + i);
        int4   n1 = __ldcs(ynv4 + i + BDIM);
        unsigned tw0 = s_tabw[i];
        unsigned tw1 = s_tabw[i + BDIM];
        process(a0, y0, n0, tw0);
        process(a1, y1, n1, tw1);
    }
    for (; i < nvec; i += BDIM) {
        float4 a = __ldcs(xv + i);
        int4   yq = __ldcs(yv4 + i);
        int4   nq = __ldcs(ynv4 + i);
        process(a, yq, nq, s_tabw[i]);
    }
    // tail scalars
    for (int c = tail0 + tid; c < NC; c += BDIM)
        scalar_at(c, ((const unsigned char*)s_tabw)[c - head]);

    __syncthreads();
    int cnt = s_cnt;

    // x-only rescan helper for fallback tiers (unreachable for bench data)
    auto rescan = [&](float thr, bool store) -> int {
        if (tid == 0) s_cnt = 0;
        __syncthreads();
        int local = 0;
        auto emit = [&](float v) {
            if (v > thr) {
                if (store) { int p = atomicAdd(&s_cnt, 1); if (p < CAP) s_cand[p] = v; }
                else local++;
            }
        };
        if (tid < head) emit(__ldg(xr + tid));
        for (int k = tid; k < nvec; k += BDIM) {
            float4 v = __ldg(xv + k);
            emit(v.x); emit(v.y); emit(v.z); emit(v.w);
        }
        for (int c = tail0 + tid; c < NC; c += BDIM) emit(__ldg(xr + c));
        if (!store && local) atomicAdd(&s_cnt, local);
        __syncthreads();
        return s_cnt;
    };

    if (cnt < 11 || cnt > CAP) {
        float thr = T2;
        cnt = rescan(thr, true);
        if (cnt < 11 || cnt > CAP) {
            float tlo, thi;
            if (cnt < 11) { thi = thr; tlo = -3.0e38f; }
            else          { tlo = thr; thi = 3.0e38f; }
            for (int it = 0; it < 120; ++it) {
                float mid = 0.5f * (tlo + thi);
                int c2 = rescan(mid, false);
                if (c2 > CAP)      tlo = mid;
                else if (c2 < 11)  thi = mid;
                else { thr = mid; break; }
                thr = mid;
            }
            cnt = rescan(thr, true);
            if (cnt > CAP) cnt = CAP;
        }
    }

    // exact 11th largest among candidates (all non-candidates are <= threshold)
    for (int k = tid; k < cnt; k += BDIM) {
        float vi = s_cand[k];
        int rank = 0;
        for (int j = 0; j < cnt; ++j) {
            float vj = s_cand[j];
            rank += (vj > vi) || (vj == vi && j < k);
        }
        if (rank == 10) s_v11 = vi;
    }
    __syncthreads();
    const float thres = fmaxf(sigmoidf_(s_v11), 0.5f);

    if (tid == 0) {
        float gs[NL];
        float umax = 0.0f;
#pragma unroll
        for (int l = 0; l < NL; ++l) {
            gs[l] = sigmoidf_(fdec(s_gmax[l]));
            umax  = fmaxf(umax, gs[l]);
        }
        int g = -1;
#pragma unroll
        for (int l = 0; l < NL; ++l)
            if (g < 0 && s_act[l]) g = l;

        float imax = 0.0f, ineg = 0.0f;
#pragma unroll
        for (int l = 0; l < NL; ++l) {
            if (l != g)  imax = fmaxf(imax, gs[l]);
            if (s_an[l]) ineg = fmaxf(ineg, gs[l]);
        }

        float loss;
        if (g < 0) {
            loss = 0.5f * rankl(thres, umax) + 0.5f * rankl(thres, ineg);
        } else {
            loss = rankl(gs[g], thres);
            if (imax > 0.0f) loss += 0.5f * rankl(thres, imax);
            loss += 0.5f * ((ineg > 0.0f) ? rankl(thres, ineg)
                                          : rankl(thres, imax));
        }
        d_loss[b] = loss;
        __threadfence();
        int done = atomicAdd(&d_done, 1);
        s_last = (done == NB - 1);
    }
    __syncthreads();

    // last finished block performs the deterministic fixed-order reduction
    if (s_last) {
        __shared__ float sh[BDIM];
        float s = 0.0f;
#pragma unroll
        for (int k = 0; k < NB / BDIM; ++k)
            s += d_loss[tid + k * BDIM];
        sh[tid] = s;
        __syncthreads();
        for (int o = BDIM / 2; o > 0; o >>= 1) {
            if (tid < o) sh[tid] += sh[tid + o];
            __syncthreads();
        }
        if (tid == 0) out[0] = sh[0];
    }
}

extern "C" void kernel_launch(void* const* d_in, const int* in_sizes, int n_in,
                              void* d_out, int out_size) {
    const float* x    = (const float*)d_in[0];
    const int*   y    = (const int*)d_in[1];
    const int*   yn   = (const int*)d_in[2];
    const void*  mask = (const void*)d_in[3];
    float*       out  = (float*)d_out;

    init_kernel<<<40, 256>>>();
    detect_kernel<<<64, 256>>>((const unsigned char*)mask);
    build_kernel<<<148, 256>>>(mask);
    loss_kernel<<<NB, BDIM>>>(x, y, yn, out);
}

// round 8
// speedup vs baseline: 1.0103x; 1.0103x over previous
#include <cuda_runtime.h>
#include <math.h>
#include <stdint.h>

#define NB   2048
#define NC   9605
#define NL   20
#define NCP  9616                    // NC rounded up to 16
#define BDIM 256
#define CAP  2048
#define T1   2.5f                    // ~60 candidates expected for N(0,1)
#define T2   1.0f
#define TOTCH ((NB * NC) / 4)        // 4,917,610 int4 chunks (exact)
#define XGRID 1024                   // single wave, 2 rows per block

// Scratch (no allocations allowed)
__device__ __align__(16) unsigned char d_tabs[4][NCP]; // shifted class->group
__device__ int   d_hist[4];
__device__ int   d_actg[NB];         // per-row group-activity bitmask (y)
__device__ int   d_ang[NB];          // per-row group-activity bitmask (y_neg)
__device__ float d_loss[NB];
__device__ int   d_done;

__global__ void __launch_bounds__(256)
init_kernel() {
    int t0 = blockIdx.x * blockDim.x + threadIdx.x;
    int gs = gridDim.x * blockDim.x;
    if (t0 == 0) {
        d_done = 0;
        d_hist[0] = d_hist[1] = d_hist[2] = d_hist[3] = 0;
    }
    for (int i = t0; i < NB; i += gs) { d_actg[i] = 0; d_ang[i] = 0; }
    uint4* p = (uint4*)d_tabs;
    const uint4 ff = make_uint4(0xFFFFFFFFu, 0xFFFFFFFFu, 0xFFFFFFFFu, 0xFFFFFFFFu);
    for (int i = t0; i < (4 * NCP) / 16; i += gs) p[i] = ff;
}

// Infer mask dtype: flag nonzero bytes by (offset mod 4) over first NL*NC bytes.
__global__ void __launch_bounds__(256)
detect_kernel(const unsigned char* __restrict__ raw) {
    const int total = NL * NC;
    const uint4* r4 = (const uint4*)raw;
    int f0 = 0, f1 = 0, f2 = 0, f3 = 0;
    int nv = total >> 4;
    for (int i = blockIdx.x * blockDim.x + threadIdx.x; i < nv;
         i += gridDim.x * blockDim.x) {
        uint4 w = __ldg(r4 + i);
        unsigned a = w.x | w.y | w.z | w.w;
        f0 |= (a & 0x000000FFu) != 0;
        f1 |= (a & 0x0000FF00u) != 0;
        f2 |= (a & 0x00FF0000u) != 0;
        f3 |= (a & 0xFF000000u) != 0;
    }
    if (blockIdx.x == 0) {
        for (int i = (nv << 4) + threadIdx.x; i < total; i += blockDim.x)
            if (raw[i]) { int m = i & 3;
                f0 |= (m == 0); f1 |= (m == 1); f2 |= (m == 2); f3 |= (m == 3); }
    }
    if (f0) atomicOr(&d_hist[0], 1);
    if (f1) atomicOr(&d_hist[1], 1);
    if (f2) atomicOr(&d_hist[2], 1);
    if (f3) atomicOr(&d_hist[3], 1);
}

__device__ __forceinline__ void tab_set(int c, unsigned char g) {
#pragma unroll
    for (int h = 0; h < 4; ++h)
        if (c >= h) d_tabs[h][c - h] = g;
}

__global__ void __launch_bounds__(256)
build_kernel(const void* __restrict__ maskv) {
    int h0 = d_hist[0], h1 = d_hist[1], h2 = d_hist[2], h3 = d_hist[3];
    int mode;  // 0 = uint8, 1 = int32, 2 = float32
    if (h0 && !h1 && !h2 && !h3)        mode = 1;
    else if (!h0 && !h1 && (h2 || h3))  mode = 2;
    else                                 mode = 0;

    const int total = NL * NC;
    const int gs = gridDim.x * blockDim.x;
    const int t0 = blockIdx.x * blockDim.x + threadIdx.x;

    if (mode != 0) {
        const int4* m4 = (const int4*)maskv;  // int32/float32: !=0 bit test
        int nv = total >> 2;
        for (int i = t0; i < nv; i += gs) {
            int4 w = __ldg(m4 + i);
            int base = i << 2;
#pragma unroll
            for (int u = 0; u < 4; ++u) {
                int bits = (u == 0) ? w.x : (u == 1) ? w.y : (u == 2) ? w.z : w.w;
                if (bits != 0) {
                    int idx = base + u;
                    tab_set(idx % NC, (unsigned char)(idx / NC));
                }
            }
        }
        for (int idx = (nv << 2) + t0; idx < total; idx += gs)
            if (((const int*)maskv)[idx] != 0)
                tab_set(idx % NC, (unsigned char)(idx / NC));
    } else {
        const unsigned char* m8 = (const unsigned char*)maskv;
        for (int idx = t0; idx < total; idx += gs)
            if (m8[idx])
                tab_set(idx % NC, (unsigned char)(idx / NC));
    }
}

// ---------------------------------------------------------------------------
// Pure 2-stream activity scan: flat int4 over the whole [B, C] arrays.
// ---------------------------------------------------------------------------
__device__ __forceinline__ void act_hit(int i, const int4& w, int* dst) {
#pragma unroll
    for (int u = 0; u < 4; ++u) {
        int v = (u == 0) ? w.x : (u == 1) ? w.y : (u == 2) ? w.z : w.w;
        if (v != 0) {
            int q   = (i << 2) + u;
            int row = q / NC;                 // cold path: plain div OK
            int cls = q - row * NC;
            unsigned char t = d_tabs[0][cls];
            if (t != 0xFF) atomicOr(&dst[row], 1 << t);
        }
    }
}

__global__ void __launch_bounds__(256)
act_kernel(const int* __restrict__ y, const int* __restrict__ yn) {
    const int gs = gridDim.x * blockDim.x;
    const int4* y4 = (const int4*)y;
    const int4* n4 = (const int4*)yn;
    int i = blockIdx.x * blockDim.x + threadIdx.x;
    for (; i + gs < TOTCH; i += 2 * gs) {
        int4 a0 = __ldcs(y4 + i);
        int4 a1 = __ldcs(y4 + i + gs);
        int4 b0 = __ldcs(n4 + i);
        int4 b1 = __ldcs(n4 + i + gs);
        if (a0.x | a0.y | a0.z | a0.w) act_hit(i,      a0, d_actg);
        if (a1.x | a1.y | a1.z | a1.w) act_hit(i + gs, a1, d_actg);
        if (b0.x | b0.y | b0.z | b0.w) act_hit(i,      b0, d_ang);
        if (b1.x | b1.y | b1.z | b1.w) act_hit(i + gs, b1, d_ang);
    }
    for (; i < TOTCH; i += gs) {
        int4 a = __ldcs(y4 + i);
        int4 b = __ldcs(n4 + i);
        if (a.x | a.y | a.z | a.w) act_hit(i, a, d_actg);
        if (b.x | b.y | b.z | b.w) act_hit(i, b, d_ang);
    }
}

__device__ __forceinline__ float sigmoidf_(float v) {
    return 1.0f / (1.0f + expf(-v));
}
__device__ __forceinline__ float rankl(float x1, float x2) {
    float d = x2 - x1 + 0.05f;
    float s = 1.0f / (1.0f + expf(-10.0f * d));
    return (d > 0.0f) ? 2.0f * s : s;
}
__device__ __forceinline__ unsigned fenc(float v) {
    unsigned u = __float_as_uint(v);
    return (u & 0x80000000u) ? ~u : (u | 0x80000000u);
}
__device__ __forceinline__ float fdec(unsigned u) {
    return (u & 0x80000000u) ? __uint_as_float(u ^ 0x80000000u)
                             : __uint_as_float(~u);
}

// ---------------------------------------------------------------------------
// x-only per-row pass: top-11 threshold candidates + per-group max; then loss
// using the activity bitmasks. 1024 blocks x 2 rows = single balanced wave.
// ---------------------------------------------------------------------------
__global__ void __launch_bounds__(BDIM, 8)
xloss_kernel(const float* __restrict__ x, float* __restrict__ out) {
    const int tid = threadIdx.x;

    __shared__ unsigned s_tabw[NCP / 4];
    __shared__ float    s_cand[CAP];
    __shared__ int      s_cnt;
    __shared__ float    s_v11;
    __shared__ unsigned s_gmax[NL];
    __shared__ int      s_last;

    for (int b = blockIdx.x; b < NB; b += XGRID) {
        const float* xr = x + (size_t)b * NC;

        if (tid == 0) s_cnt = 0;
        if (tid < NL) s_gmax[tid] = 0u;

        const int head = (int)((16u - ((unsigned)(uintptr_t)xr & 15u)) & 15u) >> 2;
        const float4* xv = (const float4*)(xr + head);
        const int nvec  = (NC - head) >> 2;
        const int tail0 = head + (nvec << 2);

        // stage shifted class->group table (L2-resident source)
        {
            const uint4* src = (const uint4*)d_tabs[head];
            uint4* dst = (uint4*)s_tabw;
            for (int i = tid; i < NCP / 16; i += BDIM) dst[i] = __ldg(src + i);
        }
        __syncthreads();

        auto process = [&](const float4& v, unsigned tw) {
            if (fmaxf(fmaxf(v.x, v.y), fmaxf(v.z, v.w)) > T1) {
                if (v.x > T1) { int p = atomicAdd(&s_cnt, 1); if (p < CAP) s_cand[p] = v.x; }
                if (v.y > T1) { int p = atomicAdd(&s_cnt, 1); if (p < CAP) s_cand[p] = v.y; }
                if (v.z > T1) { int p = atomicAdd(&s_cnt, 1); if (p < CAP) s_cand[p] = v.z; }
                if (v.w > T1) { int p = atomicAdd(&s_cnt, 1); if (p < CAP) s_cand[p] = v.w; }
            }
            if (tw != 0xFFFFFFFFu) {
                unsigned t0 =  tw        & 0xFF;
                unsigned t1 = (tw >> 8)  & 0xFF;
                unsigned t2 = (tw >> 16) & 0xFF;
                unsigned t3 = (tw >> 24) & 0xFF;
                if (t0 != 0xFF) atomicMax(&s_gmax[t0], fenc(v.x));
                if (t1 != 0xFF) atomicMax(&s_gmax[t1], fenc(v.y));
                if (t2 != 0xFF) atomicMax(&s_gmax[t2], fenc(v.z));
                if (t3 != 0xFF) atomicMax(&s_gmax[t3], fenc(v.w));
            }
        };
        auto scalar_at = [&](int c, unsigned char t) {
            float v = __ldg(xr + c);
            if (v > T1) { int p = atomicAdd(&s_cnt, 1); if (p < CAP) s_cand[p] = v; }
            if (t != 0xFF) atomicMax(&s_gmax[t], fenc(v));
        };

        if (tid < head) scalar_at(tid, d_tabs[0][tid]);

        int i = tid;
        for (; i + BDIM < nvec; i += 2 * BDIM) {
            float4 a0 = __ldcs(xv + i);
            float4 a1 = __ldcs(xv + i + BDIM);
            unsigned tw0 = s_tabw[i];
            unsigned tw1 = s_tabw[i + BDIM];
            process(a0, tw0);
            process(a1, tw1);
        }
        for (; i < nvec; i += BDIM)
            process(__ldcs(xv + i), s_tabw[i]);
        for (int c = tail0 + tid; c < NC; c += BDIM)
            scalar_at(c, ((const unsigned char*)s_tabw)[c - head]);

        __syncthreads();
        int cnt = s_cnt;

        // x-only rescan fallback tiers (unreachable for the bench data)
        auto rescan = [&](float thr, bool store) -> int {
            if (tid == 0) s_cnt = 0;
            __syncthreads();
            int local = 0;
            auto emit = [&](float v) {
                if (v > thr) {
                    if (store) { int p = atomicAdd(&s_cnt, 1); if (p < CAP) s_cand[p] = v; }
                    else local++;
                }
            };
            if (tid < head) emit(__ldg(xr + tid));
            for (int k = tid; k < nvec; k += BDIM) {
                float4 v = __ldg(xv + k);
                emit(v.x); emit(v.y); emit(v.z); emit(v.w);
            }
            for (int c = tail0 + tid; c < NC; c += BDIM) emit(__ldg(xr + c));
            if (!store && local) atomicAdd(&s_cnt, local);
            __syncthreads();
            return s_cnt;
        };

        if (cnt < 11 || cnt > CAP) {
            float thr = T2;
            cnt = rescan(thr, true);
            if (cnt < 11 || cnt > CAP) {
                float tlo, thi;
                if (cnt < 11) { thi = thr; tlo = -3.0e38f; }
                else          { tlo = thr; thi = 3.0e38f; }
                for (int it = 0; it < 120; ++it) {
                    float mid = 0.5f * (tlo + thi);
                    int c2 = rescan(mid, false);
                    if (c2 > CAP)      tlo = mid;
                    else if (c2 < 11)  thi = mid;
                    else { thr = mid; break; }
                    thr = mid;
                }
                cnt = rescan(thr, true);
                if (cnt > CAP) cnt = CAP;
            }
        }

        for (int k = tid; k < cnt; k += BDIM) {
            float vi = s_cand[k];
            int rank = 0;
            for (int j = 0; j < cnt; ++j) {
                float vj = s_cand[j];
                rank += (vj > vi) || (vj == vi && j < k);
            }
            if (rank == 10) s_v11 = vi;
        }
        __syncthreads();

        if (tid == 0) {
            const float thres = fmaxf(sigmoidf_(s_v11), 0.5f);
            const int act = d_actg[b];
            const int an  = d_ang[b];

            float gsv[NL];
            float umax = 0.0f;
#pragma unroll
            for (int l = 0; l < NL; ++l) {
                gsv[l] = sigmoidf_(fdec(s_gmax[l]));
                umax   = fmaxf(umax, gsv[l]);
            }
            int g = act ? (__ffs(act) - 1) : -1;

            float imax = 0.0f, ineg = 0.0f;
#pragma unroll
            for (int l = 0; l < NL; ++l) {
                if (l != g)          imax = fmaxf(imax, gsv[l]);
                if (an & (1 << l))   ineg = fmaxf(ineg, gsv[l]);
            }

            float loss;
            if (g < 0) {
                loss = 0.5f * rankl(thres, umax) + 0.5f * rankl(thres, ineg);
            } else {
                loss = rankl(gsv[g], thres);
                if (imax > 0.0f) loss += 0.5f * rankl(thres, imax);
                loss += 0.5f * ((ineg > 0.0f) ? rankl(thres, ineg)
                                              : rankl(thres, imax));
            }
            d_loss[b] = loss;
        }
        __syncthreads();
    }

    // completion counting + deterministic last-block reduction
    if (tid == 0) {
        __threadfence();
        int done = atomicAdd(&d_done, 1);
        s_last = (done == XGRID - 1);
    }
    __syncthreads();
    if (s_last) {
        __shared__ float sh[BDIM];
        float s = 0.0f;
#pragma unroll
        for (int k = 0; k < NB / BDIM; ++k)
            s += d_loss[tid + k * BDIM];
        sh[tid] = s;
        __syncthreads();
        for (int o = BDIM / 2; o > 0; o >>= 1) {
            if (tid < o) sh[tid] += sh[tid + o];
            __syncthreads();
        }
        if (tid == 0) out[0] = sh[0];
    }
}

extern "C" void kernel_launch(void* const* d_in, const int* in_sizes, int n_in,
                              void* d_out, int out_size) {
    const float* x    = (const float*)d_in[0];
    const int*   y    = (const int*)d_in[1];
    const int*   yn   = (const int*)d_in[2];
    const void*  mask = (const void*)d_in[3];
    float*       out  = (float*)d_out;

    init_kernel<<<40, 256>>>();
    detect_kernel<<<64, 256>>>((const unsigned char*)mask);
    build_kernel<<<148, 256>>>(mask);
    act_kernel<<<1184, 256>>>(y, yn);
    xloss_kernel<<<XGRID, BDIM>>>(x, out);
}